// round 3
// baseline (speedup 1.0000x reference)
#include <cuda_runtime.h>
#include <math.h>

// Problem constants (fixed by the reference)
#define NW      65536
#define WPT     2                  // walkers per thread (f32x2 lanes)
#define NT      (NW / WPT)         // 32768 threads
#define TPB     128
#define NBLK    (NT / TPB)         // 256 blocks  (divides 2^32 -> counter wrap safe)
#define TOTALS  512
#define WARM    128
#define NSTEPS  384
#define CH      8                  // steps per prefetch chunk
#define NCH     (TOTALS / CH)      // 64
#define WARM_CH (WARM / CH)        // 16
#define STRIDE  (NW / WPT)         // per-step stride in 64-bit units

typedef unsigned long long ull;

// Per-block partials + arrival counter (monotonic; NBLK divides 2^32).
__device__ float        g_part[8][NBLK];
__device__ unsigned int g_ctr = 0;

// ---------- f32x2 packed helpers (Blackwell-only PTX) ----------
__device__ __forceinline__ ull PKF(float a, float b) {
    ull v; asm("mov.b64 %0, {%1, %2};" : "=l"(v)
               : "r"(__float_as_uint(a)), "r"(__float_as_uint(b)));
    return v;
}
__device__ __forceinline__ ull PKU(unsigned a, unsigned b) {
    ull v; asm("mov.b64 %0, {%1, %2};" : "=l"(v) : "r"(a), "r"(b));
    return v;
}
__device__ __forceinline__ float LO(ull v) { return __uint_as_float((unsigned)v); }
__device__ __forceinline__ float HI(ull v) { return __uint_as_float((unsigned)(v >> 32)); }
__device__ __forceinline__ ull FMA2(ull a, ull b, ull c) {
    ull d; asm("fma.rn.f32x2 %0, %1, %2, %3;" : "=l"(d) : "l"(a), "l"(b), "l"(c));
    return d;
}
__device__ __forceinline__ ull MUL2(ull a, ull b) {
    ull d; asm("mul.rn.f32x2 %0, %1, %2;" : "=l"(d) : "l"(a), "l"(b));
    return d;
}
__device__ __forceinline__ ull ADD2(ull a, ull b) {
    ull d; asm("add.rn.f32x2 %0, %1, %2;" : "=l"(d) : "l"(a), "l"(b));
    return d;
}
__device__ __forceinline__ ull SPL(float a) { return PKF(a, a); }

__global__ void __launch_bounds__(TPB) vmc_kernel(
    const float* __restrict__ theta,
    const float* __restrict__ r0,
    const float* __restrict__ sdevp,
    const float* __restrict__ noise,
    const float* __restrict__ unif,
    float* __restrict__ out, int out_size)
{
    const int w = blockIdx.x * TPB + threadIdx.x;   // thread = walker pair

    const float th0 = theta[0];
    const float th1 = theta[1];
    const float th2 = theta[2];
    const float sdev = sdevp[0];

    const float kk = __fmul_rn(-2.0f, th1);  // Metropolis const (matches ref rounding)
    const float g  = 2.0f * th1;
    float s0, c0; sincosf(th0, &s0, &c0);
    const float emt = expf(-th1);
    const float C1f = -2.0f * emt * c0;      // e = C1*cosh(y) + i*C2*sinh(y)
    const float C2f =  2.0f * emt * s0;      // y = 2*th1*(r - th2)

    // Packed constants (loop-invariant; CSE'd out of the loops)
    const ull sd2  = SPL(sdev);
    const ull kk2  = SPL(kk);
    const ull mkk2 = SPL(-kk);
    const ull g2   = SPL(g);
    const ull C1v  = SPL(C1f);
    const ull C2v  = SPL(C2f);
    const ull one2 = SPL(1.0f);
    // cosh/sinh Taylor (|y| <~ 0.7, err < 1e-7)
    const ull cT1 = SPL(2.48015873e-5f), cT2 = SPL(1.38888889e-3f);
    const ull cT3 = SPL(4.16666667e-2f), cT4 = SPL(0.5f);
    const ull cS1 = SPL(1.98412698e-4f), cS2 = SPL(8.33333333e-3f);
    const ull cS3 = SPL(0.16666667f);
    // log poly (njuffa, <0.9 ulp), valid for positive normal inputs
    const ull cm1  = SPL(-1.0f);
    const ull cLA = SPL(-0.130310059f), cLB = SPL(-0.121483512f);
    const ull cLC = SPL( 0.140869141f), cLD = SPL( 0.139814854f);
    const ull cLE = SPL(-0.166846126f), cLF = SPL( 0.200120345f);
    const ull cLG = SPL(-0.249996200f), cLH = SPL( 0.333331972f);
    const ull cLI = SPL(-0.5f),         cLN2 = SPL(0.693147182f);

    // ---- state: xs = r - th2 (packed), nkx2 = -kk*xs^2 ----
    const float2 rr = ((const float2*)r0)[w];
    ull xs   = PKF(__fsub_rn(rr.x, th2), __fsub_rn(rr.y, th2));
    ull xs2s = MUL2(xs, xs);
    ull nkx2 = MUL2(mkk2, xs2s);

    const ull* np = (const ull*)noise + w;
    const ull* up = (const ull*)unif  + w;

    // Double-buffered register prefetch: 16 LDG.64 in flight
    ull nb[2][CH], ub[2][CH];
#pragma unroll
    for (int j = 0; j < CH; j++) { nb[0][j] = np[j * STRIDE]; ub[0][j] = up[j * STRIDE]; }

    ull S0 = 0, S1 = 0, S2 = 0, S3 = 0, S4 = 0, S5 = 0, S6 = 0, S7 = 0;

    int buf = 0;
    long long off = (long long)CH * STRIDE;

    // packed log(u), u positive normal in (0,1)
#define LOG2W(u, lgu) do {                                                   \
        unsigned iu0 = (unsigned)(u);                                        \
        unsigned iu1 = (unsigned)((u) >> 32);                                \
        int e0 = (int)((iu0 - 0x3f2aaaabu) & 0xff800000u);                   \
        int e1 = (int)((iu1 - 0x3f2aaaabu) & 0xff800000u);                   \
        float mm0 = __int_as_float((int)iu0 - e0);                           \
        float mm1 = __int_as_float((int)iu1 - e1);                           \
        float ie0 = (float)e0 * 1.19209290e-7f;                              \
        float ie1 = (float)e1 * 1.19209290e-7f;                              \
        ull f_ = ADD2(PKF(mm0, mm1), cm1);                                   \
        ull s_ = MUL2(f_, f_);                                               \
        ull r_ = FMA2(cLA, s_, cLB);                                         \
        ull t_ = FMA2(cLC, s_, cLD);                                         \
        r_ = FMA2(r_, s_, cLE);                                              \
        t_ = FMA2(t_, s_, cLF);                                              \
        r_ = FMA2(r_, s_, cLG);                                              \
        r_ = FMA2(t_, f_, r_);                                               \
        r_ = FMA2(r_, f_, cLH);                                              \
        r_ = FMA2(r_, f_, cLI);                                              \
        r_ = FMA2(r_, s_, f_);                                               \
        (lgu) = FMA2(PKF(ie0, ie1), cLN2, r_);                               \
    } while (0)

    // ---------------- warmup ----------------
    for (int c = 0; c < WARM_CH; c++) {
#pragma unroll
        for (int j = 0; j < CH; j++) {
            nb[buf ^ 1][j] = np[off + j * STRIDE];
            ub[buf ^ 1][j] = up[off + j * STRIDE];
        }
        off += (long long)CH * STRIDE;

#pragma unroll
        for (int j = 0; j < CH; j++) {
            ull n = nb[buf][j], u = ub[buf][j];
            ull sn  = MUL2(sd2, n);
            ull xp  = ADD2(xs, sn);
            ull xp2 = MUL2(xp, xp);
            ull lr  = FMA2(kk2, xp2, nkx2);
            ull nkc = MUL2(mkk2, xp2);
            ull lgu; LOG2W(u, lgu);
            unsigned mk0 = (LO(lgu) < LO(lr)) ? 0xffffffffu : 0u;
            unsigned mk1 = (HI(lgu) < HI(lr)) ? 0xffffffffu : 0u;
            ull mk = PKU(mk0, mk1);
            xs   = (xp  & mk) | (xs   & ~mk);
            nkx2 = (nkc & mk) | (nkx2 & ~mk);
        }
        buf ^= 1;
    }

    xs2s = MUL2(xs, xs);   // re-derive (bit-identical to accepted xp2)

    // ---------------- measurement ----------------
    for (int c = WARM_CH; c < NCH; c++) {
        if (c + 1 < NCH) {
#pragma unroll
            for (int j = 0; j < CH; j++) {
                nb[buf ^ 1][j] = np[off + j * STRIDE];
                ub[buf ^ 1][j] = up[off + j * STRIDE];
            }
            off += (long long)CH * STRIDE;
        }

#pragma unroll
        for (int j = 0; j < CH; j++) {
            ull n = nb[buf][j], u = ub[buf][j];
            ull sn  = MUL2(sd2, n);
            ull xp  = ADD2(xs, sn);
            ull xp2 = MUL2(xp, xp);
            ull lr  = FMA2(kk2, xp2, nkx2);
            ull nkc = MUL2(mkk2, xp2);
            ull lgu; LOG2W(u, lgu);
            unsigned mk0 = (LO(lgu) < LO(lr)) ? 0xffffffffu : 0u;
            unsigned mk1 = (HI(lgu) < HI(lr)) ? 0xffffffffu : 0u;
            ull mk = PKU(mk0, mk1);
            xs   = (xp  & mk) | (xs   & ~mk);
            xs2s = (xp2 & mk) | (xs2s & ~mk);
            nkx2 = (nkc & mk) | (nkx2 & ~mk);

            // energy: e = C1*cosh(y) + i*C2*sinh(y), y = g*xs
            ull y  = MUL2(g2, xs);
            ull y2 = MUL2(y, y);
            ull ch = FMA2(y2, FMA2(y2, FMA2(y2, FMA2(y2, cT1, cT2), cT3), cT4), one2);
            ull sq = FMA2(y2, FMA2(y2, FMA2(y2, cS1, cS2), cS3), one2);
            ull er = MUL2(C1v, ch);
            ull ei = MUL2(MUL2(C2v, y), sq);

            S0 = ADD2(S0, er);
            S1 = ADD2(S1, ei);
            S2 = ADD2(S2, xs);
            S3 = ADD2(S3, xs2s);
            S4 = FMA2(xs,   er, S4);
            S5 = FMA2(xs,   ei, S5);
            S6 = FMA2(xs2s, er, S6);
            S7 = FMA2(xs2s, ei, S7);
        }
        buf ^= 1;
    }

    // ---------------- block reduction ----------------
    float v0 = LO(S0) + HI(S0), v1 = LO(S1) + HI(S1);
    float v2 = LO(S2) + HI(S2), v3 = LO(S3) + HI(S3);
    float v4 = LO(S4) + HI(S4), v5 = LO(S5) + HI(S5);
    float v6 = LO(S6) + HI(S6), v7 = LO(S7) + HI(S7);

    const unsigned m = 0xffffffffu;
#pragma unroll
    for (int o = 16; o; o >>= 1) {
        v0 += __shfl_xor_sync(m, v0, o);
        v1 += __shfl_xor_sync(m, v1, o);
        v2 += __shfl_xor_sync(m, v2, o);
        v3 += __shfl_xor_sync(m, v3, o);
        v4 += __shfl_xor_sync(m, v4, o);
        v5 += __shfl_xor_sync(m, v5, o);
        v6 += __shfl_xor_sync(m, v6, o);
        v7 += __shfl_xor_sync(m, v7, o);
    }

    __shared__ float sh[8][4];
    __shared__ int sLast;
    const int lane = threadIdx.x & 31;
    const int wp   = threadIdx.x >> 5;
    if (lane == 0) {
        sh[0][wp] = v0; sh[1][wp] = v1; sh[2][wp] = v2; sh[3][wp] = v3;
        sh[4][wp] = v4; sh[5][wp] = v5; sh[6][wp] = v6; sh[7][wp] = v7;
    }
    __syncthreads();
    if (threadIdx.x < 32) {
        const int q  = threadIdx.x >> 2;
        const int wj = threadIdx.x & 3;
        float v = sh[q][wj];
        v += __shfl_down_sync(m, v, 2, 4);
        v += __shfl_down_sync(m, v, 1, 4);
        if (wj == 0) g_part[q][blockIdx.x] = v;
    }
    __threadfence();
    __syncthreads();
    if (threadIdx.x == 0) {
        unsigned old = atomicAdd(&g_ctr, 1u);
        sLast = ((old % NBLK) == (NBLK - 1)) ? 1 : 0;
    }
    __syncthreads();

    // ---------------- last block: final reduce + output ----------------
    if (sLast) {
        const int q = threadIdx.x >> 4;    // 8 quantities x 16 lanes
        const int l = threadIdx.x & 15;
        float v = 0.f;
#pragma unroll
        for (int i = l; i < NBLK; i += 16) v += __ldcg(&g_part[q][i]);
#pragma unroll
        for (int o = 8; o; o >>= 1) v += __shfl_down_sync(m, v, o, 16);

        __shared__ float s8[8];
        if (l == 0) s8[q] = v;
        __syncthreads();

        if (threadIdx.x == 0) {
            const float inv = 1.0f / ((float)NW * (float)NSTEPS);
            const float Ser   = s8[0] * inv;   // mean(Re e)
            const float Sei   = s8[1] * inv;   // mean(Im e)
            const float Sxs   = s8[2] * inv;   // mean(xs) = mean(r) - th2
            const float Sx2   = s8[3] * inv;   // mean(xs^2)
            const float Sxer  = s8[4] * inv;   // mean(xs * Re e)
            const float Sxei  = s8[5] * inv;   // mean(xs * Im e)
            const float Sx2er = s8[6] * inv;
            const float Sx2ei = s8[7] * inv;

            if (out_size == 14) {
                const float Sr   = Sxs + th2;
                const float Srer = Sxer + th2 * Ser;
                const float Srei = Sxei + th2 * Sei;
                float2* o2 = (float2*)out;
                o2[0] = make_float2(Ser, Sei);
                o2[1] = make_float2(0.0f, Sr);
                o2[2] = make_float2(Sx2, 0.0f);
                o2[3] = make_float2(g * Sxs, 0.0f);
                o2[4] = make_float2(Srei, -Srer);
                o2[5] = make_float2(Sx2er, Sx2ei);
                o2[6] = make_float2(g * Sxer, g * Sxei);
            } else {
                out[0] = Ser;                  // Es.re
                out[1] = 0.0f;                 // Ds0.re
                out[2] = Sx2;                  // Ds1.re
                out[3] = g * Sxs;              // Ds2.re
                out[4] = Sxei + th2 * Sei;     // EDs0.re = mean(r*Im e)
                out[5] = Sx2er;                // EDs1.re
                out[6] = g * Sxer;             // EDs2.re
            }
        }
    }
}

extern "C" void kernel_launch(void* const* d_in, const int* in_sizes, int n_in,
                              void* d_out, int out_size)
{
    const float* theta = (const float*)d_in[0];
    const float* r0    = (const float*)d_in[1];
    const float* sdev  = (const float*)d_in[2];
    const float* noise = (const float*)d_in[3];
    const float* unif  = (const float*)d_in[4];

    vmc_kernel<<<NBLK, TPB>>>(theta, r0, sdev, noise, unif, (float*)d_out, out_size);
}

// round 4
// speedup vs baseline: 1.9766x; 1.9766x over previous
#include <cuda_runtime.h>
#include <math.h>
#include <stdint.h>

// Problem constants (fixed by the reference)
#define NW      65536
#define TPB     128
#define NBLK    256                // NW / (TPB*2 walkers per thread)
#define TOTALS  512
#define WARM    128
#define NSTEPS  384
#define CH      8                  // steps per smem chunk
#define NCH     (TOTALS / CH)      // 64
#define WARM_CH (WARM / CH)        // 16
#define ROWB    ((size_t)NW * 4)   // gmem bytes per step-row (262144)

typedef unsigned long long ull;

// Per-block partials + arrival counter (monotonic; NBLK divides 2^32 -> replay safe).
__device__ float        g_part[8][NBLK];
__device__ unsigned int g_ctr = 0;

// ---------- f32x2 packed helpers ----------
__device__ __forceinline__ ull PKF(float a, float b) {
    ull v; asm("mov.b64 %0, {%1, %2};" : "=l"(v)
               : "r"(__float_as_uint(a)), "r"(__float_as_uint(b)));
    return v;
}
__device__ __forceinline__ ull PKU(unsigned a, unsigned b) {
    ull v; asm("mov.b64 %0, {%1, %2};" : "=l"(v) : "r"(a), "r"(b));
    return v;
}
__device__ __forceinline__ float LO(ull v) { return __uint_as_float((unsigned)v); }
__device__ __forceinline__ float HI(ull v) { return __uint_as_float((unsigned)(v >> 32)); }
__device__ __forceinline__ ull FMA2(ull a, ull b, ull c) {
    ull d; asm("fma.rn.f32x2 %0, %1, %2, %3;" : "=l"(d) : "l"(a), "l"(b), "l"(c));
    return d;
}
__device__ __forceinline__ ull MUL2(ull a, ull b) {
    ull d; asm("mul.rn.f32x2 %0, %1, %2;" : "=l"(d) : "l"(a), "l"(b));
    return d;
}
__device__ __forceinline__ ull ADD2(ull a, ull b) {
    ull d; asm("add.rn.f32x2 %0, %1, %2;" : "=l"(d) : "l"(a), "l"(b));
    return d;
}
__device__ __forceinline__ ull SPL(float a) { return PKF(a, a); }

__device__ __forceinline__ void cp16(uint32_t dst, const void* src) {
    asm volatile("cp.async.cg.shared.global [%0], [%1], 16;" :: "r"(dst), "l"(src));
}

__global__ void __launch_bounds__(TPB) vmc_kernel(
    const float* __restrict__ theta,
    const float* __restrict__ r0,
    const float* __restrict__ sdevp,
    const float* __restrict__ noise,
    const float* __restrict__ unif,
    float* __restrict__ out, int out_size)
{
    // ---- smem staging: 2 bufs x 8 rows x 128 ull per array ----
    __shared__ ull smN[2][CH * TPB];   // 16 KB
    __shared__ ull smU[2][CH * TPB];   // 16 KB
    __shared__ float sh[8][4];
    __shared__ float s8[8];
    __shared__ int   sLast;

    const int tid = threadIdx.x;
    const int blk = blockIdx.x;
    const int w   = blk * TPB + tid;       // walker-pair index

    const float th0 = theta[0];
    const float th1 = theta[1];
    const float th2 = theta[2];
    const float sdev = sdevp[0];

    // Trajectory constants: kk EXACTLY as reference rounds it (validated R2/R3)
    const float kk = __fmul_rn(-2.0f, th1);
    const float gf = 2.0f * th1;

    const ull sd2  = SPL(sdev);
    const ull kk2  = SPL(kk);
    const ull mkk2 = SPL(-kk);

    // exp constants (e^lr = 2^(lr*log2e), magic rounding, deg-5 2^f poly)
    const ull l2e   = SPL(1.44269504f);
    const ull magic = SPL(12582912.0f);     // 1.5 * 2^23
    const ull nmag  = SPL(-12582912.0f);
    const ull mone  = SPL(-1.0f);
    const ull e5 = SPL(1.33335581e-3f), e4 = SPL(9.61812910e-3f);
    const ull e3 = SPL(5.55041086e-2f), e2 = SPL(2.40226507e-1f);
    const ull e1 = SPL(6.93147182e-1f), e0 = SPL(1.0f);

    // Energy polys in t = xs^2 (coeffs folded with C1, C2*g, powers of g^2; fp64 once)
    {
    }
    const double dth0 = (double)th0, dth1 = (double)th1;
    const double dg  = 2.0 * dth1, g2d = dg * dg;
    const double dC1 = -2.0 * exp(-dth1) * cos(dth0);
    const double dC2 =  2.0 * exp(-dth1) * sin(dth0);
    const ull A0 = SPL((float)dC1);
    const ull A1 = SPL((float)(dC1 * g2d / 2.0));
    const ull A2 = SPL((float)(dC1 * g2d * g2d / 24.0));
    const ull A3 = SPL((float)(dC1 * g2d * g2d * g2d / 720.0));
    const ull A4 = SPL((float)(dC1 * g2d * g2d * g2d * g2d / 40320.0));
    const ull B0 = SPL((float)(dC2 * dg));
    const ull B1 = SPL((float)(dC2 * dg * g2d / 6.0));
    const ull B2 = SPL((float)(dC2 * dg * g2d * g2d / 120.0));
    const ull B3 = SPL((float)(dC2 * dg * g2d * g2d * g2d / 5040.0));

    // ---- state: xs = r - th2, xs2s = xs^2, nkx2 = -kk*xs^2 ----
    const float2 rr = ((const float2*)r0)[w];
    ull xs   = PKF(__fsub_rn(rr.x, th2), __fsub_rn(rr.y, th2));
    ull xs2s = MUL2(xs, xs);
    ull nkx2 = MUL2(mkk2, xs2s);

    // ---- cp.async per-thread geometry ----
    const uint32_t baseN = (uint32_t)__cvta_generic_to_shared(&smN[0][0]);
    const uint32_t baseU = (uint32_t)__cvta_generic_to_shared(&smU[0][0]);
    const int c16  = tid & 63;
    const int rsel = tid >> 6;                      // 0 or 1
    const size_t sliceOff = (size_t)blk * 1024 + (size_t)c16 * 16;
    const char* gN = (const char*)noise + sliceOff;
    const char* gU = (const char*)unif  + sliceOff;

    // issue chunk starting at step s0 into buffer b
#define ISSUE_CHUNK(s0, b) do {                                              \
        const char* _n = gN + (size_t)(s0) * ROWB;                           \
        const char* _u = gU + (size_t)(s0) * ROWB;                           \
        _Pragma("unroll")                                                    \
        for (int _k = 0; _k < 4; _k++) {                                     \
            int _row = _k * 2 + rsel;                                        \
            uint32_t _d = (uint32_t)((b) * (CH*TPB*8) + _row * 1024 + c16 * 16); \
            cp16(baseN + _d, _n + (size_t)_row * ROWB);                      \
            cp16(baseU + _d, _u + (size_t)_row * ROWB);                      \
        }                                                                    \
        asm volatile("cp.async.commit_group;" ::: "memory");                 \
    } while (0)

    // metro step: updates xs, xs2s, nkx2 from packed (n,u)
#define METRO(n, u) do {                                                     \
        ull sn  = MUL2(sd2, (n));                                            \
        ull xp  = ADD2(xs, sn);                                              \
        ull xp2 = MUL2(xp, xp);                                              \
        ull lr  = FMA2(kk2, xp2, nkx2);                                      \
        /* ep = exp(lr) via 2^(z), z = lr*log2e */                           \
        ull z  = MUL2(l2e, lr);                                              \
        ull fz = ADD2(z, magic);                                             \
        ull kf = ADD2(fz, nmag);                                             \
        ull f  = FMA2(kf, mone, z);                                          \
        ull p  = FMA2(e5, f, e4);                                            \
        p = FMA2(p, f, e3); p = FMA2(p, f, e2);                              \
        p = FMA2(p, f, e1); p = FMA2(p, f, e0);                              \
        unsigned _klo = (unsigned)fz, _khi = (unsigned)(fz >> 32);           \
        unsigned _slo = (_klo - 0x4B400000u + 127u) << 23;                   \
        unsigned _shi = (_khi - 0x4B400000u + 127u) << 23;                   \
        ull ep = MUL2(p, PKU(_slo, _shi));                                   \
        unsigned mk0 = (LO(u) < LO(ep)) ? 0xffffffffu : 0u;                  \
        unsigned mk1 = (HI(u) < HI(ep)) ? 0xffffffffu : 0u;                  \
        ull mk = PKU(mk0, mk1);                                              \
        xs   = (xp  & mk) | (xs   & ~mk);                                    \
        xs2s = (xp2 & mk) | (xs2s & ~mk);                                    \
        nkx2 = MUL2(mkk2, xs2s);                                             \
    } while (0)

    ull S0 = 0, S1 = 0, S2 = 0, S3 = 0, S4 = 0, S5 = 0, S6 = 0, S7 = 0;

    ISSUE_CHUNK(0, 0);
    int buf = 0;

    for (int c = 0; c < NCH; c++) {
        __syncthreads();   // compute of chunk c-1 finished -> safe to overwrite buf^1
        if (c + 1 < NCH) {
            ISSUE_CHUNK((c + 1) * CH, buf ^ 1);
            asm volatile("cp.async.wait_group 1;" ::: "memory");
        } else {
            asm volatile("cp.async.wait_group 0;" ::: "memory");
        }
        __syncthreads();   // chunk c visible to all threads

        const ull* rn = &smN[buf][0];
        const ull* ru = &smU[buf][0];

        if (c < WARM_CH) {
#pragma unroll
            for (int j = 0; j < CH; j++) {
                ull n = rn[j * TPB + tid];
                ull u = ru[j * TPB + tid];
                METRO(n, u);
            }
        } else {
#pragma unroll
            for (int j = 0; j < CH; j++) {
                ull n = rn[j * TPB + tid];
                ull u = ru[j * TPB + tid];
                METRO(n, u);

                // e = er + i*ei, polys in t = xs^2
                ull t  = xs2s;
                ull er = FMA2(A4, t, A3);
                er = FMA2(er, t, A2); er = FMA2(er, t, A1); er = FMA2(er, t, A0);
                ull pb = FMA2(B3, t, B2);
                pb = FMA2(pb, t, B1); pb = FMA2(pb, t, B0);
                ull ei = MUL2(xs, pb);

                S0 = ADD2(S0, er);
                S1 = ADD2(S1, ei);
                S2 = ADD2(S2, xs);
                S3 = ADD2(S3, t);
                S4 = FMA2(xs, er, S4);
                S5 = FMA2(xs, ei, S5);
                S6 = FMA2(t,  er, S6);
                S7 = FMA2(t,  ei, S7);
            }
        }
        buf ^= 1;
    }

    // ---------------- block reduction ----------------
    float v0 = LO(S0) + HI(S0), v1 = LO(S1) + HI(S1);
    float v2 = LO(S2) + HI(S2), v3 = LO(S3) + HI(S3);
    float v4 = LO(S4) + HI(S4), v5 = LO(S5) + HI(S5);
    float v6 = LO(S6) + HI(S6), v7 = LO(S7) + HI(S7);

    const unsigned m = 0xffffffffu;
#pragma unroll
    for (int o = 16; o; o >>= 1) {
        v0 += __shfl_xor_sync(m, v0, o);
        v1 += __shfl_xor_sync(m, v1, o);
        v2 += __shfl_xor_sync(m, v2, o);
        v3 += __shfl_xor_sync(m, v3, o);
        v4 += __shfl_xor_sync(m, v4, o);
        v5 += __shfl_xor_sync(m, v5, o);
        v6 += __shfl_xor_sync(m, v6, o);
        v7 += __shfl_xor_sync(m, v7, o);
    }

    const int lane = tid & 31;
    const int wp   = tid >> 5;
    if (lane == 0) {
        sh[0][wp] = v0; sh[1][wp] = v1; sh[2][wp] = v2; sh[3][wp] = v3;
        sh[4][wp] = v4; sh[5][wp] = v5; sh[6][wp] = v6; sh[7][wp] = v7;
    }
    __syncthreads();
    if (tid < 32) {
        const int q  = tid >> 2;
        const int wj = tid & 3;
        float v = sh[q][wj];
        v += __shfl_down_sync(m, v, 2, 4);
        v += __shfl_down_sync(m, v, 1, 4);
        if (wj == 0) g_part[q][blk] = v;
    }
    __threadfence();
    __syncthreads();
    if (tid == 0) {
        unsigned old = atomicAdd(&g_ctr, 1u);
        sLast = ((old % NBLK) == (NBLK - 1)) ? 1 : 0;
    }
    __syncthreads();

    // ---------------- last block: final reduce + output ----------------
    if (sLast) {
        const int q = tid >> 4;    // 8 quantities x 16 lanes
        const int l = tid & 15;
        float v = 0.f;
#pragma unroll
        for (int i = l; i < NBLK; i += 16) v += __ldcg(&g_part[q][i]);
#pragma unroll
        for (int o = 8; o; o >>= 1) v += __shfl_down_sync(m, v, o, 16);

        if (l == 0 && q < 8) s8[q] = v;
        __syncthreads();

        if (tid == 0) {
            const float inv = 1.0f / ((float)NW * (float)NSTEPS);
            const float Ser   = s8[0] * inv;
            const float Sei   = s8[1] * inv;
            const float Sxs   = s8[2] * inv;   // mean(r) - th2
            const float Sx2   = s8[3] * inv;
            const float Sxer  = s8[4] * inv;
            const float Sxei  = s8[5] * inv;
            const float Sx2er = s8[6] * inv;
            const float Sx2ei = s8[7] * inv;

            if (out_size == 14) {
                const float Sr   = Sxs + th2;
                const float Srer = Sxer + th2 * Ser;
                const float Srei = Sxei + th2 * Sei;
                float2* o2 = (float2*)out;
                o2[0] = make_float2(Ser, Sei);
                o2[1] = make_float2(0.0f, Sr);
                o2[2] = make_float2(Sx2, 0.0f);
                o2[3] = make_float2(gf * Sxs, 0.0f);
                o2[4] = make_float2(Srei, -Srer);
                o2[5] = make_float2(Sx2er, Sx2ei);
                o2[6] = make_float2(gf * Sxer, gf * Sxei);
            } else {
                out[0] = Ser;                  // Es.re
                out[1] = 0.0f;                 // Ds0.re
                out[2] = Sx2;                  // Ds1.re
                out[3] = gf * Sxs;             // Ds2.re
                out[4] = Sxei + th2 * Sei;     // EDs0.re
                out[5] = Sx2er;                // EDs1.re
                out[6] = gf * Sxer;            // EDs2.re
            }
        }
    }
}

extern "C" void kernel_launch(void* const* d_in, const int* in_sizes, int n_in,
                              void* d_out, int out_size)
{
    const float* theta = (const float*)d_in[0];
    const float* r0    = (const float*)d_in[1];
    const float* sdev  = (const float*)d_in[2];
    const float* noise = (const float*)d_in[3];
    const float* unif  = (const float*)d_in[4];

    vmc_kernel<<<NBLK, TPB>>>(theta, r0, sdev, noise, unif, (float*)d_out, out_size);
}

// round 5
// speedup vs baseline: 2.0436x; 1.0339x over previous
#include <cuda_runtime.h>
#include <math.h>
#include <stdint.h>

// Problem constants (fixed by the reference)
#define NW      65536
#define TPB     256
#define NBLK    128                // NW / (TPB*2 walkers/thread); divides 2^32
#define TOTALS  512
#define WARM    128
#define NSTEPS  384
#define CH      8                  // steps per chunk
#define NCH     (TOTALS / CH)      // 64
#define WARM_CH (WARM / CH)        // 16
#define STAGES  4
#define ROWB    ((size_t)NW * 4)   // gmem bytes per step-row
// smem ring geometry (in ull): stage = [N: CH*TPB][U: CH*TPB]
#define UOFF    (CH * TPB)         // 2048 ull
#define STG     (2 * CH * TPB)     // 4096 ull = 32 KB
#define SMEM_BYTES (STAGES * STG * 8)   // 128 KB

typedef unsigned long long ull;

__device__ float        g_part[8][NBLK];
__device__ unsigned int g_ctr = 0;

// ---------- f32x2 packed helpers ----------
__device__ __forceinline__ ull PKF(float a, float b) {
    ull v; asm("mov.b64 %0, {%1, %2};" : "=l"(v)
               : "r"(__float_as_uint(a)), "r"(__float_as_uint(b)));
    return v;
}
__device__ __forceinline__ ull PKU(unsigned a, unsigned b) {
    ull v; asm("mov.b64 %0, {%1, %2};" : "=l"(v) : "r"(a), "r"(b));
    return v;
}
__device__ __forceinline__ float LO(ull v) { return __uint_as_float((unsigned)v); }
__device__ __forceinline__ float HI(ull v) { return __uint_as_float((unsigned)(v >> 32)); }
__device__ __forceinline__ ull FMA2(ull a, ull b, ull c) {
    ull d; asm("fma.rn.f32x2 %0, %1, %2, %3;" : "=l"(d) : "l"(a), "l"(b), "l"(c));
    return d;
}
__device__ __forceinline__ ull MUL2(ull a, ull b) {
    ull d; asm("mul.rn.f32x2 %0, %1, %2;" : "=l"(d) : "l"(a), "l"(b));
    return d;
}
__device__ __forceinline__ ull ADD2(ull a, ull b) {
    ull d; asm("add.rn.f32x2 %0, %1, %2;" : "=l"(d) : "l"(a), "l"(b));
    return d;
}
__device__ __forceinline__ ull SPL(float a) { return PKF(a, a); }

__device__ __forceinline__ void cp16(uint32_t dst, const void* src) {
    asm volatile("cp.async.cg.shared.global [%0], [%1], 16;" :: "r"(dst), "l"(src));
}

__global__ void __launch_bounds__(TPB) vmc_kernel(
    const float* __restrict__ theta,
    const float* __restrict__ r0,
    const float* __restrict__ sdevp,
    const float* __restrict__ noise,
    const float* __restrict__ unif,
    float* __restrict__ out, int out_size)
{
    extern __shared__ ull ring[];            // STAGES * STG ull
    float* shred = (float*)ring;             // aliased reduction scratch (post-loop)

    const int tid = threadIdx.x;
    const int blk = blockIdx.x;
    const int w   = blk * TPB + tid;         // walker-pair index

    const float th0 = theta[0];
    const float th1 = theta[1];
    const float th2 = theta[2];
    const float sdev = sdevp[0];

    // Trajectory constants: kk EXACTLY as reference rounds it (validated R2-R4)
    const float kk = __fmul_rn(-2.0f, th1);
    const float gf = 2.0f * th1;

    const ull sd2  = SPL(sdev);
    const ull kk2  = SPL(kk);
    const ull mkk2 = SPL(-kk);

    // exp constants (accept test: u < e^lr), magic-round + deg-5 2^f poly
    const ull l2e   = SPL(1.44269504f);
    const ull magic = SPL(12582912.0f);
    const ull nmag  = SPL(-12582912.0f);
    const ull mone  = SPL(-1.0f);
    const ull e5 = SPL(1.33335581e-3f), e4 = SPL(9.61812910e-3f);
    const ull e3 = SPL(5.55041086e-2f), e2 = SPL(2.40226507e-1f);
    const ull e1 = SPL(6.93147182e-1f), e0 = SPL(1.0f);

    // Energy polys in t = xs^2, coeffs folded in fp64 once
    const double dth0 = (double)th0, dth1 = (double)th1;
    const double dg  = 2.0 * dth1, g2d = dg * dg;
    const double dC1 = -2.0 * exp(-dth1) * cos(dth0);
    const double dC2 =  2.0 * exp(-dth1) * sin(dth0);
    const ull A0 = SPL((float)dC1);
    const ull A1 = SPL((float)(dC1 * g2d / 2.0));
    const ull A2 = SPL((float)(dC1 * g2d * g2d / 24.0));
    const ull A3 = SPL((float)(dC1 * g2d * g2d * g2d / 720.0));
    const ull B0 = SPL((float)(dC2 * dg));
    const ull B1 = SPL((float)(dC2 * dg * g2d / 6.0));
    const ull B2 = SPL((float)(dC2 * dg * g2d * g2d / 120.0));

    // ---- state ----
    const float2 rr = ((const float2*)r0)[w];
    ull xs   = PKF(__fsub_rn(rr.x, th2), __fsub_rn(rr.y, th2));
    ull xs2s = MUL2(xs, xs);
    ull nkx2 = MUL2(mkk2, xs2s);

    // ---- cp.async geometry: chunk row = 2048 B, 128 granules of 16 B ----
    const uint32_t base = (uint32_t)__cvta_generic_to_shared(ring);
    const int c16  = tid & 127;               // granule within row
    const int rsel = tid >> 7;                // 0/1: rows rsel, rsel+2, rsel+4, rsel+6
    const size_t sliceOff = (size_t)blk * 2048 + (size_t)c16 * 16;
    const char* gN = (const char*)noise + sliceOff;
    const char* gU = (const char*)unif  + sliceOff;

#define ISSUE_CHUNK(s0, stg) do {                                            \
        const char* _n = gN + (size_t)(s0) * ROWB;                           \
        const char* _u = gU + (size_t)(s0) * ROWB;                           \
        uint32_t _sb = base + (uint32_t)(stg) * (STG * 8);                   \
        _Pragma("unroll")                                                    \
        for (int _k = 0; _k < 4; _k++) {                                     \
            int _row = _k * 2 + rsel;                                        \
            uint32_t _d = (uint32_t)(_row * 2048 + c16 * 16);                \
            cp16(_sb + _d,               _n + (size_t)_row * ROWB);          \
            cp16(_sb + UOFF * 8 + _d,    _u + (size_t)_row * ROWB);          \
        }                                                                    \
        asm volatile("cp.async.commit_group;" ::: "memory");                 \
    } while (0)

#define METRO(n, u) do {                                                     \
        ull sn  = MUL2(sd2, (n));                                            \
        ull xp  = ADD2(xs, sn);                                              \
        ull xp2 = MUL2(xp, xp);                                              \
        ull lr  = FMA2(kk2, xp2, nkx2);                                      \
        ull z  = MUL2(l2e, lr);                                              \
        ull fz = ADD2(z, magic);                                             \
        ull kf = ADD2(fz, nmag);                                             \
        ull f  = FMA2(kf, mone, z);                                          \
        ull p  = FMA2(e5, f, e4);                                            \
        p = FMA2(p, f, e3); p = FMA2(p, f, e2);                              \
        p = FMA2(p, f, e1); p = FMA2(p, f, e0);                              \
        unsigned _klo = (unsigned)fz, _khi = (unsigned)(fz >> 32);           \
        unsigned _slo = (_klo - 0x4B400000u + 127u) << 23;                   \
        unsigned _shi = (_khi - 0x4B400000u + 127u) << 23;                   \
        ull ep = MUL2(p, PKU(_slo, _shi));                                   \
        unsigned mk0 = (LO(u) < LO(ep)) ? 0xffffffffu : 0u;                  \
        unsigned mk1 = (HI(u) < HI(ep)) ? 0xffffffffu : 0u;                  \
        ull mk = PKU(mk0, mk1);                                              \
        xs   = (xp & mk) | (xs & ~mk);                                       \
        xs2s = MUL2(xs, xs);          /* bit-identical to selected xp2 */    \
        nkx2 = MUL2(mkk2, xs2s);                                             \
    } while (0)

    ull S0 = 0, S1 = 0, S2 = 0, S3 = 0, S4 = 0, S5 = 0, S6 = 0, S7 = 0;

    // prologue: 3 chunks in flight
    ISSUE_CHUNK(0 * CH, 0);
    ISSUE_CHUNK(1 * CH, 1);
    ISSUE_CHUNK(2 * CH, 2);

    for (int c = 0; c < NCH; c++) {
        // commits so far = 3 + c; need group c done -> <= 2 younger outstanding
        asm volatile("cp.async.wait_group 2;" ::: "memory");
        __syncthreads();   // visibility of chunk c; all threads done reading slot (c-1)&3

        if (c + 3 < NCH) {
            ISSUE_CHUNK((c + 3) * CH, (c + 3) & 3);
        } else {
            asm volatile("cp.async.commit_group;" ::: "memory");  // keep count uniform
        }

        const ull* st = ring + (size_t)(c & 3) * STG;

        if (c < WARM_CH) {
#pragma unroll
            for (int j = 0; j < CH; j++) {
                ull n = st[j * TPB + tid];
                ull u = st[UOFF + j * TPB + tid];
                METRO(n, u);
            }
        } else {
#pragma unroll
            for (int j = 0; j < CH; j++) {
                ull n = st[j * TPB + tid];
                ull u = st[UOFF + j * TPB + tid];
                METRO(n, u);

                ull t  = xs2s;
                ull er = FMA2(A3, t, A2);
                er = FMA2(er, t, A1); er = FMA2(er, t, A0);
                ull pb = FMA2(B2, t, B1);
                pb = FMA2(pb, t, B0);
                ull ei = MUL2(xs, pb);

                S0 = ADD2(S0, er);
                S1 = ADD2(S1, ei);
                S2 = ADD2(S2, xs);
                S3 = ADD2(S3, t);
                S4 = FMA2(xs, er, S4);
                S5 = FMA2(xs, ei, S5);
                S6 = FMA2(t,  er, S6);
                S7 = FMA2(t,  ei, S7);
            }
        }
    }

    // ---------------- block reduction (ring now dead; alias scratch) ----------------
    float v0 = LO(S0) + HI(S0), v1 = LO(S1) + HI(S1);
    float v2 = LO(S2) + HI(S2), v3 = LO(S3) + HI(S3);
    float v4 = LO(S4) + HI(S4), v5 = LO(S5) + HI(S5);
    float v6 = LO(S6) + HI(S6), v7 = LO(S7) + HI(S7);

    const unsigned m = 0xffffffffu;
#pragma unroll
    for (int o = 16; o; o >>= 1) {
        v0 += __shfl_xor_sync(m, v0, o);
        v1 += __shfl_xor_sync(m, v1, o);
        v2 += __shfl_xor_sync(m, v2, o);
        v3 += __shfl_xor_sync(m, v3, o);
        v4 += __shfl_xor_sync(m, v4, o);
        v5 += __shfl_xor_sync(m, v5, o);
        v6 += __shfl_xor_sync(m, v6, o);
        v7 += __shfl_xor_sync(m, v7, o);
    }

    float* sh   = shred;            // [8][8]
    float* s8   = shred + 64;       // [8]
    int*  sLast = (int*)(shred + 72);

    __syncthreads();                 // all reads of ring complete before aliasing
    const int lane = tid & 31;
    const int wp   = tid >> 5;       // 8 warps
    if (lane == 0) {
        sh[0 * 8 + wp] = v0; sh[1 * 8 + wp] = v1;
        sh[2 * 8 + wp] = v2; sh[3 * 8 + wp] = v3;
        sh[4 * 8 + wp] = v4; sh[5 * 8 + wp] = v5;
        sh[6 * 8 + wp] = v6; sh[7 * 8 + wp] = v7;
    }
    __syncthreads();
    if (tid < 64) {
        const int q  = tid >> 3;
        const int wj = tid & 7;
        float v = sh[q * 8 + wj];
        v += __shfl_down_sync(m, v, 4, 8);
        v += __shfl_down_sync(m, v, 2, 8);
        v += __shfl_down_sync(m, v, 1, 8);
        if (wj == 0) g_part[q][blk] = v;
    }
    __threadfence();
    __syncthreads();
    if (tid == 0) {
        unsigned old = atomicAdd(&g_ctr, 1u);
        *sLast = ((old % NBLK) == (NBLK - 1)) ? 1 : 0;
    }
    __syncthreads();

    // ---------------- last block: final reduce + output ----------------
    if (*sLast) {
        if (tid < 128) {
            const int q = tid >> 4;    // 8 quantities x 16 lanes
            const int l = tid & 15;
            float v = 0.f;
#pragma unroll
            for (int i = l; i < NBLK; i += 16) v += __ldcg(&g_part[q][i]);
#pragma unroll
            for (int o = 8; o; o >>= 1) v += __shfl_down_sync(m, v, o, 16);
            if (l == 0) s8[q] = v;
        }
        __syncthreads();

        if (tid == 0) {
            const float inv = 1.0f / ((float)NW * (float)NSTEPS);
            const float Ser   = s8[0] * inv;
            const float Sei   = s8[1] * inv;
            const float Sxs   = s8[2] * inv;   // mean(r) - th2
            const float Sx2   = s8[3] * inv;
            const float Sxer  = s8[4] * inv;
            const float Sxei  = s8[5] * inv;
            const float Sx2er = s8[6] * inv;
            const float Sx2ei = s8[7] * inv;

            if (out_size == 14) {
                const float Sr   = Sxs + th2;
                const float Srer = Sxer + th2 * Ser;
                const float Srei = Sxei + th2 * Sei;
                float2* o2 = (float2*)out;
                o2[0] = make_float2(Ser, Sei);
                o2[1] = make_float2(0.0f, Sr);
                o2[2] = make_float2(Sx2, 0.0f);
                o2[3] = make_float2(gf * Sxs, 0.0f);
                o2[4] = make_float2(Srei, -Srer);
                o2[5] = make_float2(Sx2er, Sx2ei);
                o2[6] = make_float2(gf * Sxer, gf * Sxei);
            } else {
                out[0] = Ser;                  // Es.re
                out[1] = 0.0f;                 // Ds0.re
                out[2] = Sx2;                  // Ds1.re
                out[3] = gf * Sxs;             // Ds2.re
                out[4] = Sxei + th2 * Sei;     // EDs0.re
                out[5] = Sx2er;                // EDs1.re
                out[6] = gf * Sxer;            // EDs2.re
            }
        }
    }
}

extern "C" void kernel_launch(void* const* d_in, const int* in_sizes, int n_in,
                              void* d_out, int out_size)
{
    const float* theta = (const float*)d_in[0];
    const float* r0    = (const float*)d_in[1];
    const float* sdev  = (const float*)d_in[2];
    const float* noise = (const float*)d_in[3];
    const float* unif  = (const float*)d_in[4];

    // Idempotent, non-stream API: capture-safe.
    cudaFuncSetAttribute(vmc_kernel, cudaFuncAttributeMaxDynamicSharedMemorySize,
                         SMEM_BYTES);

    vmc_kernel<<<NBLK, TPB, SMEM_BYTES>>>(theta, r0, sdev, noise, unif,
                                          (float*)d_out, out_size);
}

// round 6
// speedup vs baseline: 2.1207x; 1.0377x over previous
#include <cuda_runtime.h>
#include <math.h>
#include <stdint.h>

// Problem constants (fixed by the reference)
#define NW      65536
#define TPB     128
#define PPB     256                // walker pairs per block (2 chains/thread)
#define NBLK    128                // 32768 pairs / 256; divides 2^32
#define TOTALS  512
#define WARM    128
#define NSTEPS  384
#define CH      8                  // steps per chunk
#define NCH     (TOTALS / CH)      // 64
#define WARM_CH (WARM / CH)        // 16
#define ROWB    ((size_t)NW * 4)   // gmem bytes per step-row
// smem ring (ull units): stage = [N: CH*PPB][U: CH*PPB]
#define UOFF    (CH * PPB)         // 2048 ull
#define STG     (2 * CH * PPB)     // 4096 ull = 32 KB
#define SMEM_BYTES (4 * STG * 8)   // 128 KB

typedef unsigned long long ull;

__device__ float        g_part[8][NBLK];
__device__ unsigned int g_ctr = 0;

// ---------- f32x2 packed helpers ----------
__device__ __forceinline__ ull PKF(float a, float b) {
    ull v; asm("mov.b64 %0, {%1, %2};" : "=l"(v)
               : "r"(__float_as_uint(a)), "r"(__float_as_uint(b)));
    return v;
}
__device__ __forceinline__ ull PKU(unsigned a, unsigned b) {
    ull v; asm("mov.b64 %0, {%1, %2};" : "=l"(v) : "r"(a), "r"(b));
    return v;
}
__device__ __forceinline__ float LO(ull v) { return __uint_as_float((unsigned)v); }
__device__ __forceinline__ float HI(ull v) { return __uint_as_float((unsigned)(v >> 32)); }
__device__ __forceinline__ ull FMA2(ull a, ull b, ull c) {
    ull d; asm("fma.rn.f32x2 %0, %1, %2, %3;" : "=l"(d) : "l"(a), "l"(b), "l"(c));
    return d;
}
__device__ __forceinline__ ull MUL2(ull a, ull b) {
    ull d; asm("mul.rn.f32x2 %0, %1, %2;" : "=l"(d) : "l"(a), "l"(b));
    return d;
}
__device__ __forceinline__ ull ADD2(ull a, ull b) {
    ull d; asm("add.rn.f32x2 %0, %1, %2;" : "=l"(d) : "l"(a), "l"(b));
    return d;
}
__device__ __forceinline__ ull SPL(float a) { return PKF(a, a); }

__device__ __forceinline__ void cp16(uint32_t dst, const void* src) {
    asm volatile("cp.async.cg.shared.global [%0], [%1], 16;" :: "r"(dst), "l"(src));
}

__global__ void __launch_bounds__(TPB) vmc_kernel(
    const float* __restrict__ theta,
    const float* __restrict__ r0,
    const float* __restrict__ sdevp,
    const float* __restrict__ noise,
    const float* __restrict__ unif,
    float* __restrict__ out, int out_size)
{
    extern __shared__ ull ring[];
    float* shred = (float*)ring;             // aliased reduction scratch

    const int tid = threadIdx.x;
    const int blk = blockIdx.x;

    const float th0 = theta[0];
    const float th1 = theta[1];
    const float th2 = theta[2];
    const float sdev = sdevp[0];

    const float kk = __fmul_rn(-2.0f, th1);   // reference rounding (validated)
    const float gf = 2.0f * th1;

    const ull sd2   = SPL(sdev);
    // log2e folded into Metropolis constant: z = lkz*xp^2 + nhz, nhz = -lkz*xs^2
    const float lkzf = kk * 1.44269504f;
    const ull lkz2  = SPL(lkzf);
    const ull nlkz2 = SPL(-lkzf);

    // 2^f poly on f in [-0.5, 0.5] (deg-5, ~1e-7 rel), magic rounding
    const ull magic = SPL(12582912.0f);
    const ull nmag  = SPL(-12582912.0f);
    const ull mone  = SPL(-1.0f);
    const ull e5 = SPL(1.33335581e-3f), e4 = SPL(9.61812910e-3f);
    const ull e3 = SPL(5.55041086e-2f), e2 = SPL(2.40226507e-1f);
    const ull e1 = SPL(6.93147182e-1f), e0 = SPL(1.0f);

    // Energy polys in t = xs^2, coeffs folded in fp64 once
    const double dth0 = (double)th0, dth1 = (double)th1;
    const double dg = 2.0 * dth1, g2d = dg * dg;
    const double dC1 = -2.0 * exp(-dth1) * cos(dth0);
    const double dC2 =  2.0 * exp(-dth1) * sin(dth0);
    const ull A0 = SPL((float)dC1);
    const ull A1 = SPL((float)(dC1 * g2d / 2.0));
    const ull A2 = SPL((float)(dC1 * g2d * g2d / 24.0));
    const ull A3 = SPL((float)(dC1 * g2d * g2d * g2d / 720.0));
    const ull B0 = SPL((float)(dC2 * dg));
    const ull B1 = SPL((float)(dC2 * dg * g2d / 6.0));
    const ull B2 = SPL((float)(dC2 * dg * g2d * g2d / 120.0));

    // ---- two independent chains: pairs A = blk*256+tid, B = +128 ----
    const float2 rA = ((const float2*)r0)[blk * PPB + tid];
    const float2 rB = ((const float2*)r0)[blk * PPB + 128 + tid];
    ull xsA  = PKF(__fsub_rn(rA.x, th2), __fsub_rn(rA.y, th2));
    ull xsB  = PKF(__fsub_rn(rB.x, th2), __fsub_rn(rB.y, th2));
    ull xs2A = MUL2(xsA, xsA), xs2B = MUL2(xsB, xsB);
    ull nhzA = MUL2(nlkz2, xs2A), nhzB = MUL2(nlkz2, xs2B);

    // ---- cp.async geometry: row = 256 pairs = 2048 B = 128 granules ----
    const uint32_t base = (uint32_t)__cvta_generic_to_shared(ring);
    const size_t sliceOff = (size_t)blk * 2048 + (size_t)tid * 16;
    const char* gN = (const char*)noise + sliceOff;
    const char* gU = (const char*)unif  + sliceOff;

#define ISSUE_CHUNK(s0, stg) do {                                            \
        const char* _n = gN + (size_t)(s0) * ROWB;                           \
        const char* _u = gU + (size_t)(s0) * ROWB;                           \
        uint32_t _sb = base + (uint32_t)(stg) * (STG * 8);                   \
        _Pragma("unroll")                                                    \
        for (int _r = 0; _r < CH; _r++) {                                    \
            uint32_t _d = (uint32_t)(_r * 2048 + tid * 16);                  \
            cp16(_sb + _d,            _n + (size_t)_r * ROWB);               \
            cp16(_sb + UOFF * 8 + _d, _u + (size_t)_r * ROWB);               \
        }                                                                    \
        asm volatile("cp.async.commit_group;" ::: "memory");                 \
    } while (0)

    // warmup metro: updates XS, NHZ only
#define METRO_W(n, u, XS, NHZ) do {                                          \
        ull sn  = MUL2(sd2, (n));                                            \
        ull xp  = ADD2(XS, sn);                                              \
        ull xp2 = MUL2(xp, xp);                                              \
        ull z   = FMA2(lkz2, xp2, NHZ);                                      \
        ull fz  = ADD2(z, magic);                                            \
        ull kf  = ADD2(fz, nmag);                                            \
        ull f   = FMA2(kf, mone, z);                                         \
        ull p   = FMA2(e5, f, e4);                                           \
        p = FMA2(p, f, e3); p = FMA2(p, f, e2);                              \
        p = FMA2(p, f, e1); p = FMA2(p, f, e0);                              \
        ull nhc = MUL2(nlkz2, xp2);                                          \
        unsigned eplo = (unsigned)p        + (((unsigned)fz        - 0x4B400000u) << 23); \
        unsigned ephi = (unsigned)(p >> 32) + (((unsigned)(fz >> 32) - 0x4B400000u) << 23); \
        unsigned mk0 = ((unsigned)(u)        < eplo) ? 0xffffffffu : 0u;     \
        unsigned mk1 = ((unsigned)((u) >> 32) < ephi) ? 0xffffffffu : 0u;    \
        ull mk = PKU(mk0, mk1);                                              \
        XS  = (xp  & mk) | (XS  & ~mk);                                      \
        NHZ = (nhc & mk) | (NHZ & ~mk);                                      \
    } while (0)

    // measurement metro: also maintains XS2
#define METRO_M(n, u, XS, XS2, NHZ) do {                                     \
        ull sn  = MUL2(sd2, (n));                                            \
        ull xp  = ADD2(XS, sn);                                              \
        ull xp2 = MUL2(xp, xp);                                              \
        ull z   = FMA2(lkz2, xp2, NHZ);                                      \
        ull fz  = ADD2(z, magic);                                            \
        ull kf  = ADD2(fz, nmag);                                            \
        ull f   = FMA2(kf, mone, z);                                         \
        ull p   = FMA2(e5, f, e4);                                           \
        p = FMA2(p, f, e3); p = FMA2(p, f, e2);                              \
        p = FMA2(p, f, e1); p = FMA2(p, f, e0);                              \
        ull nhc = MUL2(nlkz2, xp2);                                          \
        unsigned eplo = (unsigned)p        + (((unsigned)fz        - 0x4B400000u) << 23); \
        unsigned ephi = (unsigned)(p >> 32) + (((unsigned)(fz >> 32) - 0x4B400000u) << 23); \
        unsigned mk0 = ((unsigned)(u)        < eplo) ? 0xffffffffu : 0u;     \
        unsigned mk1 = ((unsigned)((u) >> 32) < ephi) ? 0xffffffffu : 0u;    \
        ull mk = PKU(mk0, mk1);                                              \
        XS  = (xp  & mk) | (XS  & ~mk);                                      \
        XS2 = (xp2 & mk) | (XS2 & ~mk);                                      \
        NHZ = (nhc & mk) | (NHZ & ~mk);                                      \
    } while (0)

#define MEAS(XS, XS2) do {                                                   \
        ull t  = XS2;                                                        \
        ull er = FMA2(A3, t, A2);                                            \
        er = FMA2(er, t, A1); er = FMA2(er, t, A0);                          \
        ull pb = FMA2(B2, t, B1);                                            \
        pb = FMA2(pb, t, B0);                                                \
        ull ei = MUL2(XS, pb);                                               \
        S0 = ADD2(S0, er);                                                   \
        S1 = ADD2(S1, ei);                                                   \
        S2 = ADD2(S2, XS);                                                   \
        S3 = ADD2(S3, t);                                                    \
        S4 = FMA2(XS, er, S4);                                               \
        S5 = FMA2(XS, ei, S5);                                               \
        S6 = FMA2(t,  er, S6);                                               \
        S7 = FMA2(t,  ei, S7);                                               \
    } while (0)

    ull S0 = 0, S1 = 0, S2 = 0, S3 = 0, S4 = 0, S5 = 0, S6 = 0, S7 = 0;

    ISSUE_CHUNK(0 * CH, 0);
    ISSUE_CHUNK(1 * CH, 1);
    ISSUE_CHUNK(2 * CH, 2);

    for (int c = 0; c < NCH; c++) {
        asm volatile("cp.async.wait_group 2;" ::: "memory");
        __syncthreads();

        if (c + 3 < NCH) {
            ISSUE_CHUNK((c + 3) * CH, (c + 3) & 3);
        } else {
            asm volatile("cp.async.commit_group;" ::: "memory");
        }

        const ull* st = ring + (size_t)(c & 3) * STG;

        if (c < WARM_CH) {
#pragma unroll
            for (int j = 0; j < CH; j++) {
                ull nA = st[j * PPB + tid];
                ull uA = st[UOFF + j * PPB + tid];
                ull nB = st[j * PPB + 128 + tid];
                ull uB = st[UOFF + j * PPB + 128 + tid];
                METRO_W(nA, uA, xsA, nhzA);
                METRO_W(nB, uB, xsB, nhzB);
            }
            if (c == WARM_CH - 1) {   // re-derive squares (bit-identical)
                xs2A = MUL2(xsA, xsA);
                xs2B = MUL2(xsB, xsB);
            }
        } else {
#pragma unroll
            for (int j = 0; j < CH; j++) {
                ull nA = st[j * PPB + tid];
                ull uA = st[UOFF + j * PPB + tid];
                ull nB = st[j * PPB + 128 + tid];
                ull uB = st[UOFF + j * PPB + 128 + tid];
                METRO_M(nA, uA, xsA, xs2A, nhzA);
                METRO_M(nB, uB, xsB, xs2B, nhzB);
                MEAS(xsA, xs2A);
                MEAS(xsB, xs2B);
            }
        }
    }

    // ---------------- block reduction (4 warps) ----------------
    float v0 = LO(S0) + HI(S0), v1 = LO(S1) + HI(S1);
    float v2 = LO(S2) + HI(S2), v3 = LO(S3) + HI(S3);
    float v4 = LO(S4) + HI(S4), v5 = LO(S5) + HI(S5);
    float v6 = LO(S6) + HI(S6), v7 = LO(S7) + HI(S7);

    const unsigned m = 0xffffffffu;
#pragma unroll
    for (int o = 16; o; o >>= 1) {
        v0 += __shfl_xor_sync(m, v0, o);
        v1 += __shfl_xor_sync(m, v1, o);
        v2 += __shfl_xor_sync(m, v2, o);
        v3 += __shfl_xor_sync(m, v3, o);
        v4 += __shfl_xor_sync(m, v4, o);
        v5 += __shfl_xor_sync(m, v5, o);
        v6 += __shfl_xor_sync(m, v6, o);
        v7 += __shfl_xor_sync(m, v7, o);
    }

    float* sh   = shred;            // [8][4]
    float* s8   = shred + 32;       // [8]
    int*  sLast = (int*)(shred + 40);

    __syncthreads();                // ring reads done before aliasing
    const int lane = tid & 31;
    const int wp   = tid >> 5;      // 4 warps
    if (lane == 0) {
        sh[0 * 4 + wp] = v0; sh[1 * 4 + wp] = v1;
        sh[2 * 4 + wp] = v2; sh[3 * 4 + wp] = v3;
        sh[4 * 4 + wp] = v4; sh[5 * 4 + wp] = v5;
        sh[6 * 4 + wp] = v6; sh[7 * 4 + wp] = v7;
    }
    __syncthreads();
    if (tid < 32) {
        const int q  = tid >> 2;
        const int wj = tid & 3;
        float v = sh[q * 4 + wj];
        v += __shfl_down_sync(m, v, 2, 4);
        v += __shfl_down_sync(m, v, 1, 4);
        if (wj == 0) g_part[q][blk] = v;
    }
    __threadfence();
    __syncthreads();
    if (tid == 0) {
        unsigned old = atomicAdd(&g_ctr, 1u);
        *sLast = ((old % NBLK) == (NBLK - 1)) ? 1 : 0;
    }
    __syncthreads();

    // ---------------- last block: final reduce + output ----------------
    if (*sLast) {
        const int q = tid >> 4;     // 8 quantities x 16 lanes
        const int l = tid & 15;
        float v = 0.f;
#pragma unroll
        for (int i = l; i < NBLK; i += 16) v += __ldcg(&g_part[q][i]);
#pragma unroll
        for (int o = 8; o; o >>= 1) v += __shfl_down_sync(m, v, o, 16);
        if (l == 0) s8[q] = v;
        __syncthreads();

        if (tid == 0) {
            const float inv = 1.0f / ((float)NW * (float)NSTEPS);
            const float Ser   = s8[0] * inv;
            const float Sei   = s8[1] * inv;
            const float Sxs   = s8[2] * inv;   // mean(r) - th2
            const float Sx2   = s8[3] * inv;
            const float Sxer  = s8[4] * inv;
            const float Sxei  = s8[5] * inv;
            const float Sx2er = s8[6] * inv;
            const float Sx2ei = s8[7] * inv;

            if (out_size == 14) {
                const float Sr   = Sxs + th2;
                const float Srer = Sxer + th2 * Ser;
                const float Srei = Sxei + th2 * Sei;
                float2* o2 = (float2*)out;
                o2[0] = make_float2(Ser, Sei);
                o2[1] = make_float2(0.0f, Sr);
                o2[2] = make_float2(Sx2, 0.0f);
                o2[3] = make_float2(gf * Sxs, 0.0f);
                o2[4] = make_float2(Srei, -Srer);
                o2[5] = make_float2(Sx2er, Sx2ei);
                o2[6] = make_float2(gf * Sxer, gf * Sxei);
            } else {
                out[0] = Ser;                  // Es.re
                out[1] = 0.0f;                 // Ds0.re
                out[2] = Sx2;                  // Ds1.re
                out[3] = gf * Sxs;             // Ds2.re
                out[4] = Sxei + th2 * Sei;     // EDs0.re
                out[5] = Sx2er;                // EDs1.re
                out[6] = gf * Sxer;            // EDs2.re
            }
        }
    }
}

extern "C" void kernel_launch(void* const* d_in, const int* in_sizes, int n_in,
                              void* d_out, int out_size)
{
    const float* theta = (const float*)d_in[0];
    const float* r0    = (const float*)d_in[1];
    const float* sdev  = (const float*)d_in[2];
    const float* noise = (const float*)d_in[3];
    const float* unif  = (const float*)d_in[4];

    cudaFuncSetAttribute(vmc_kernel, cudaFuncAttributeMaxDynamicSharedMemorySize,
                         SMEM_BYTES);

    vmc_kernel<<<NBLK, TPB, SMEM_BYTES>>>(theta, r0, sdev, noise, unif,
                                          (float*)d_out, out_size);
}